// round 1
// baseline (speedup 1.0000x reference)
#include <cuda_runtime.h>
#include <cuda_bf16.h>
#include <cstdint>
#include <math.h>

#define N_ROWS 8192
#define H_DIM  1024
#define INV_T  (1.0f/0.07f)

// ---------------- scratch (device globals; no runtime allocation) ----------
__device__ __nv_bfloat16 g_A[(size_t)N_ROWS * H_DIM];   // normalized source (bf16)
__device__ __nv_bfloat16 g_B[(size_t)N_ROWS * H_DIM];   // normalized target (bf16)
__device__ float g_sim[(size_t)N_ROWS * N_ROWS];        // 256 MB similarity matrix
__device__ float g_logl[N_ROWS];
__device__ int   g_pos[N_ROWS];
__device__ float g_nn[N_ROWS];

// ---------------- kernel 1: row L2-normalize -> bf16 -----------------------
__global__ __launch_bounds__(256) void norm_kernel(const float* __restrict__ src,
                                                   const float* __restrict__ tgt) {
    int row = blockIdx.x;                       // 0..16383
    const float* in;
    __nv_bfloat16* out;
    if (row < N_ROWS) { in = src + (size_t)row * H_DIM;            out = g_A + (size_t)row * H_DIM; }
    else              { in = tgt + (size_t)(row - N_ROWS) * H_DIM; out = g_B + (size_t)(row - N_ROWS) * H_DIM; }

    int t = threadIdx.x;
    float v[4];
    float ss = 0.f;
#pragma unroll
    for (int j = 0; j < 4; j++) { v[j] = in[t + 256 * j]; ss += v[j] * v[j]; }
#pragma unroll
    for (int o = 16; o; o >>= 1) ss += __shfl_xor_sync(0xffffffffu, ss, o);
    __shared__ float red[8];
    if ((t & 31) == 0) red[t >> 5] = ss;
    __syncthreads();
    float total = red[0] + red[1] + red[2] + red[3] + red[4] + red[5] + red[6] + red[7];
    float nrm = sqrtf(total);
    float sc = 1.0f / fmaxf(nrm, 1e-12f);
#pragma unroll
    for (int j = 0; j < 4; j++) out[t + 256 * j] = __float2bfloat16(v[j] * sc);
}

// ---------------- kernel 2: bf16 GEMM  sim = A @ B^T (fp32 out) ------------
// CTA tile 128x128, BK=32, 8 warps (4x2), warp tile 32x64, mma m16n8k16.
__device__ __forceinline__ void cp16(void* smem, const void* g) {
    uint32_t s = (uint32_t)__cvta_generic_to_shared(smem);
    asm volatile("cp.async.cg.shared.global [%0], [%1], 16;" :: "r"(s), "l"(g));
}

__global__ __launch_bounds__(256) void gemm_kernel() {
    __shared__ __align__(16) __nv_bfloat16 As[2][128][40];  // 40 = 32 + 8 pad (80B rows, conflict-free ldmatrix)
    __shared__ __align__(16) __nv_bfloat16 Bs[2][128][40];

    const int tid  = threadIdx.x;
    const int lane = tid & 31;
    const int warp = tid >> 5;
    const int wm = (warp & 3) * 32;
    const int wn = (warp >> 2) * 64;
    const int brow = blockIdx.y * 128;
    const int bcol = blockIdx.x * 128;

    float acc[2][8][4];
#pragma unroll
    for (int i = 0; i < 2; i++)
#pragma unroll
        for (int j = 0; j < 8; j++)
#pragma unroll
            for (int k = 0; k < 4; k++) acc[i][j][k] = 0.f;

    auto loadTiles = [&](int s, int k0) {
        for (int c = tid; c < 512; c += 256) {
            int r = c >> 2, kc = (c & 3) << 3;
            cp16(&As[s][r][kc], g_A + (size_t)(brow + r) * H_DIM + k0 + kc);
            cp16(&Bs[s][r][kc], g_B + (size_t)(bcol + r) * H_DIM + k0 + kc);
        }
    };

    loadTiles(0, 0);
    asm volatile("cp.async.commit_group;");
    int s = 0;

    for (int kt = 0; kt < H_DIM / 32; kt++) {
        asm volatile("cp.async.wait_group 0;");
        __syncthreads();
        if (kt + 1 < H_DIM / 32) {
            loadTiles(s ^ 1, (kt + 1) * 32);
            asm volatile("cp.async.commit_group;");
        }
#pragma unroll
        for (int ks = 0; ks < 32; ks += 16) {
            uint32_t a[2][4], b[8][2];
#pragma unroll
            for (int im = 0; im < 2; im++) {
                uint32_t addr = (uint32_t)__cvta_generic_to_shared(
                    &As[s][wm + im * 16 + (lane & 15)][ks + ((lane >> 4) << 3)]);
                asm volatile("ldmatrix.sync.aligned.m8n8.x4.shared.b16 {%0,%1,%2,%3}, [%4];"
                             : "=r"(a[im][0]), "=r"(a[im][1]), "=r"(a[im][2]), "=r"(a[im][3])
                             : "r"(addr));
            }
#pragma unroll
            for (int ib = 0; ib < 4; ib++) {
                uint32_t addr = (uint32_t)__cvta_generic_to_shared(
                    &Bs[s][wn + ib * 16 + ((lane >> 4) << 3) + (lane & 7)][ks + (((lane >> 3) & 1) << 3)]);
                uint32_t r0, r1, r2, r3;
                asm volatile("ldmatrix.sync.aligned.m8n8.x4.shared.b16 {%0,%1,%2,%3}, [%4];"
                             : "=r"(r0), "=r"(r1), "=r"(r2), "=r"(r3) : "r"(addr));
                b[2 * ib][0] = r0; b[2 * ib][1] = r1;
                b[2 * ib + 1][0] = r2; b[2 * ib + 1][1] = r3;
            }
#pragma unroll
            for (int im = 0; im < 2; im++)
#pragma unroll
                for (int in = 0; in < 8; in++)
                    asm volatile("mma.sync.aligned.m16n8k16.row.col.f32.bf16.bf16.f32 "
                                 "{%0,%1,%2,%3},{%4,%5,%6,%7},{%8,%9},{%0,%1,%2,%3};"
                                 : "+f"(acc[im][in][0]), "+f"(acc[im][in][1]),
                                   "+f"(acc[im][in][2]), "+f"(acc[im][in][3])
                                 : "r"(a[im][0]), "r"(a[im][1]), "r"(a[im][2]), "r"(a[im][3]),
                                   "r"(b[in][0]), "r"(b[in][1]));
        }
        s ^= 1;
        __syncthreads();
    }

    // epilogue: fp32 stores (32B-sector coalesced per 4-lane group)
#pragma unroll
    for (int im = 0; im < 2; im++) {
        int r0 = brow + wm + im * 16 + (lane >> 2);
#pragma unroll
        for (int in = 0; in < 8; in++) {
            int c = bcol + wn + in * 8 + ((lane & 3) << 1);
            *(float2*)&g_sim[(size_t)r0 * N_ROWS + c]       = make_float2(acc[im][in][0], acc[im][in][1]);
            *(float2*)&g_sim[(size_t)(r0 + 8) * N_ROWS + c] = make_float2(acc[im][in][2], acc[im][in][3]);
        }
    }
}

// ---------------- fast exp on FMA pipe (avoids MUFU bottleneck) ------------
__device__ __forceinline__ float fexp(float x) {
    // exp(x), valid for x in [-87, 0]; rel err ~2e-5 (deg-6 Taylor of 2^f)
    float t = x * 1.4426950408889634f;
    float fl = floorf(t);
    float f = t - fl;
    float p = 1.5403530e-4f;
    p = fmaf(p, f, 1.3333558e-3f);
    p = fmaf(p, f, 9.6181291e-3f);
    p = fmaf(p, f, 5.5504110e-2f);
    p = fmaf(p, f, 2.4022651e-1f);
    p = fmaf(p, f, 6.9314718e-1f);
    p = fmaf(p, f, 1.0f);
    int e = (int)fl;
    return __int_as_float((uint32_t)(e + 127) << 23) * p;
}

// ---------------- kernel 3: per-row argmax + logsumexp ---------------------
__global__ __launch_bounds__(256) void row_reduce() {
    __shared__ float srow[N_ROWS];       // 32 KB row stash
    __shared__ float sm[256];
    __shared__ int   si[256];
    int row = blockIdx.x, t = threadIdx.x;
    const float* p = g_sim + (size_t)row * N_ROWS;

    float m = -3.402823e38f; int bi = 0;
    for (int j = t; j < N_ROWS; j += 256) {
        float v = p[j];
        srow[j] = v;
        if (v > m) { m = v; bi = j; }   // ascending j -> first occurrence kept
    }
    sm[t] = m; si[t] = bi;
    __syncthreads();
    for (int s2 = 128; s2 > 0; s2 >>= 1) {
        if (t < s2) {
            float om = sm[t + s2]; int oi = si[t + s2];
            if (om > sm[t] || (om == sm[t] && oi < si[t])) { sm[t] = om; si[t] = oi; }
        }
        __syncthreads();
    }
    float rowm = sm[0]; int rowi = si[0];
    __syncthreads();

    float acc = 0.f;
    for (int j = t; j < N_ROWS; j += 256)
        acc += fexp((srow[j] - rowm) * INV_T);
    sm[t] = acc;
    __syncthreads();
    for (int s2 = 128; s2 > 0; s2 >>= 1) {
        if (t < s2) sm[t] += sm[t + s2];
        __syncthreads();
    }
    if (t == 0) {
        g_logl[row] = logf(sm[0]);   // -logp at argmax (positive logit == row max)
        g_pos[row] = rowi;
    }
}

// ---------------- kernel 4: nn_sim[i] = <B[pos[i]], B[pos[i+1]]> -----------
__global__ __launch_bounds__(128) void nn_kernel() {
    int i = blockIdx.x;              // 0..N-2
    int t = threadIdx.x;
    const __nv_bfloat16* u = g_B + (size_t)g_pos[i]     * H_DIM;
    const __nv_bfloat16* v = g_B + (size_t)g_pos[i + 1] * H_DIM;
    float acc = 0.f;
    for (int j = t; j < H_DIM; j += 128)
        acc += __bfloat162float(u[j]) * __bfloat162float(v[j]);
#pragma unroll
    for (int o = 16; o; o >>= 1) acc += __shfl_xor_sync(0xffffffffu, acc, o);
    __shared__ float red[4];
    if ((t & 31) == 0) red[t >> 5] = acc;
    __syncthreads();
    if (t == 0) g_nn[i] = red[0] + red[1] + red[2] + red[3];
}

// ---------------- kernel 5: final deterministic reduction ------------------
__global__ __launch_bounds__(256) void final_kernel(float* __restrict__ out) {
    __shared__ float s1[256], s2[256];
    int t = threadIdx.x;
    float a = 0.f, b = 0.f;
    for (int j = t; j < N_ROWS; j += 256) a += g_logl[j];
    for (int j = t; j < N_ROWS - 1; j += 256) b += g_nn[j];
    s1[t] = a; s2[t] = b;
    __syncthreads();
    for (int s = 128; s > 0; s >>= 1) {
        if (t < s) { s1[t] += s1[t + s]; s2[t] += s2[t + s]; }
        __syncthreads();
    }
    if (t == 0) {
        out[0] = s1[0] / (float)N_ROWS;                // l_contrastive = mean(log l_i)
        out[1] = 1.0f - s2[0] / (float)(N_ROWS - 1);   // l_contextual
    }
}

// ---------------- launcher --------------------------------------------------
extern "C" void kernel_launch(void* const* d_in, const int* in_sizes, int n_in,
                              void* d_out, int out_size) {
    const float* h_source = (const float*)d_in[0];
    const float* h_target = (const float*)d_in[1];
    // d_in[2], d_in[3]: masks (all true) — unused.
    float* out = (float*)d_out;

    norm_kernel<<<2 * N_ROWS, 256>>>(h_source, h_target);
    dim3 grid(N_ROWS / 128, N_ROWS / 128);
    gemm_kernel<<<grid, 256>>>();
    row_reduce<<<N_ROWS, 256>>>();
    nn_kernel<<<N_ROWS - 1, 128>>>();
    final_kernel<<<1, 256>>>(out);
}

// round 3
// speedup vs baseline: 1.1355x; 1.1355x over previous
#include <cuda_runtime.h>
#include <cuda_bf16.h>
#include <cstdint>
#include <math.h>

#define N_ROWS 8192
#define H_DIM  1024
#define NTILE  64                   // N_ROWS / 128 column tiles
#define INV_T  (1.0f/0.07f)

// ---------------- scratch (device globals; no runtime allocation) ----------
__device__ __nv_bfloat16 g_A[(size_t)N_ROWS * H_DIM];   // normalized source (bf16)
__device__ __nv_bfloat16 g_B[(size_t)N_ROWS * H_DIM];   // normalized target (bf16)
__device__ float g_pmax[(size_t)N_ROWS * NTILE];        // per-(row, coltile) max
__device__ int   g_pidx[(size_t)N_ROWS * NTILE];        // per-(row, coltile) argmax (global col)
__device__ float g_psum[(size_t)N_ROWS * NTILE];        // per-(row, coltile) sum exp((s-tilemax)/T)
__device__ float g_logl[N_ROWS];
__device__ int   g_pos[N_ROWS];
__device__ float g_nn[N_ROWS];

// ---------------- fast exp on FMA pipe (avoids MUFU bottleneck) ------------
__device__ __forceinline__ float fexp(float x) {
    // exp(x), valid for x in [-87, 0]; rel err ~1.3e-5 (deg-6 of 2^f)
    float t = x * 1.4426950408889634f;
    float fl = floorf(t);
    float f = t - fl;
    float p = 1.5403530e-4f;
    p = fmaf(p, f, 1.3333558e-3f);
    p = fmaf(p, f, 9.6181291e-3f);
    p = fmaf(p, f, 5.5504110e-2f);
    p = fmaf(p, f, 2.4022651e-1f);
    p = fmaf(p, f, 6.9314718e-1f);
    p = fmaf(p, f, 1.0f);
    int e = (int)fl;
    return __int_as_float((uint32_t)(e + 127) << 23) * p;
}

// ---------------- kernel 1: row L2-normalize -> bf16 -----------------------
__global__ __launch_bounds__(256) void norm_kernel(const float* __restrict__ src,
                                                   const float* __restrict__ tgt) {
    int row = blockIdx.x;                       // 0..16383
    const float* in;
    __nv_bfloat16* out;
    if (row < N_ROWS) { in = src + (size_t)row * H_DIM;            out = g_A + (size_t)row * H_DIM; }
    else              { in = tgt + (size_t)(row - N_ROWS) * H_DIM; out = g_B + (size_t)(row - N_ROWS) * H_DIM; }

    int t = threadIdx.x;
    float v[4];
    float ss = 0.f;
#pragma unroll
    for (int j = 0; j < 4; j++) { v[j] = in[t + 256 * j]; ss += v[j] * v[j]; }
#pragma unroll
    for (int o = 16; o; o >>= 1) ss += __shfl_xor_sync(0xffffffffu, ss, o);
    __shared__ float red[8];
    if ((t & 31) == 0) red[t >> 5] = ss;
    __syncthreads();
    float total = red[0] + red[1] + red[2] + red[3] + red[4] + red[5] + red[6] + red[7];
    float sc = 1.0f / fmaxf(sqrtf(total), 1e-12f);
#pragma unroll
    for (int j = 0; j < 4; j++) out[t + 256 * j] = __float2bfloat16(v[j] * sc);
}

// ---------------- kernel 2: fused GEMM + per-tile softmax partials ---------
// CTA tile 128x128, BK=32, 8 warps (4 row x 2 col), warp tile 32x64.
// Epilogue reduces the 128-col tile per row to (max, argmax, sumexp) partials.
// INVARIANT: g_psum is relative to g_pmax (the tile-wide row max).
__device__ __forceinline__ void cp16(void* smem, const void* g) {
    uint32_t s = (uint32_t)__cvta_generic_to_shared(smem);
    asm volatile("cp.async.cg.shared.global [%0], [%1], 16;" :: "r"(s), "l"(g));
}

__global__ __launch_bounds__(256) void gemm_fused_kernel() {
    __shared__ __align__(16) __nv_bfloat16 As[2][128][40];  // +8 pad, conflict-free ldmatrix
    __shared__ __align__(16) __nv_bfloat16 Bs[2][128][40];
    __shared__ float s_max[128][2];
    __shared__ int   s_idx[128][2];
    __shared__ float s_sum[128][2];

    const int tid  = threadIdx.x;
    const int lane = tid & 31;
    const int warp = tid >> 5;
    const int wm = (warp & 3) * 32;
    const int wn = (warp >> 2) * 64;
    const int wcol = warp >> 2;              // 0 or 1
    const int brow = blockIdx.y * 128;
    const int bcol = blockIdx.x * 128;

    float acc[2][8][4];
#pragma unroll
    for (int i = 0; i < 2; i++)
#pragma unroll
        for (int j = 0; j < 8; j++)
#pragma unroll
            for (int k = 0; k < 4; k++) acc[i][j][k] = 0.f;

    auto loadTiles = [&](int s, int k0) {
        for (int c = tid; c < 512; c += 256) {
            int r = c >> 2, kc = (c & 3) << 3;
            cp16(&As[s][r][kc], g_A + (size_t)(brow + r) * H_DIM + k0 + kc);
            cp16(&Bs[s][r][kc], g_B + (size_t)(bcol + r) * H_DIM + k0 + kc);
        }
    };

    loadTiles(0, 0);
    asm volatile("cp.async.commit_group;");
    int s = 0;

    for (int kt = 0; kt < H_DIM / 32; kt++) {
        asm volatile("cp.async.wait_group 0;");
        __syncthreads();
        if (kt + 1 < H_DIM / 32) {
            loadTiles(s ^ 1, (kt + 1) * 32);
            asm volatile("cp.async.commit_group;");
        }
#pragma unroll
        for (int ks = 0; ks < 32; ks += 16) {
            uint32_t a[2][4], b[8][2];
#pragma unroll
            for (int im = 0; im < 2; im++) {
                uint32_t addr = (uint32_t)__cvta_generic_to_shared(
                    &As[s][wm + im * 16 + (lane & 15)][ks + ((lane >> 4) << 3)]);
                asm volatile("ldmatrix.sync.aligned.m8n8.x4.shared.b16 {%0,%1,%2,%3}, [%4];"
                             : "=r"(a[im][0]), "=r"(a[im][1]), "=r"(a[im][2]), "=r"(a[im][3])
                             : "r"(addr));
            }
#pragma unroll
            for (int ib = 0; ib < 4; ib++) {
                uint32_t addr = (uint32_t)__cvta_generic_to_shared(
                    &Bs[s][wn + ib * 16 + ((lane >> 4) << 3) + (lane & 7)][ks + (((lane >> 3) & 1) << 3)]);
                uint32_t r0, r1, r2, r3;
                asm volatile("ldmatrix.sync.aligned.m8n8.x4.shared.b16 {%0,%1,%2,%3}, [%4];"
                             : "=r"(r0), "=r"(r1), "=r"(r2), "=r"(r3) : "r"(addr));
                b[2 * ib][0] = r0; b[2 * ib][1] = r1;
                b[2 * ib + 1][0] = r2; b[2 * ib + 1][1] = r3;
            }
#pragma unroll
            for (int im = 0; im < 2; im++)
#pragma unroll
                for (int in = 0; in < 8; in++)
                    asm volatile("mma.sync.aligned.m16n8k16.row.col.f32.bf16.bf16.f32 "
                                 "{%0,%1,%2,%3},{%4,%5,%6,%7},{%8,%9},{%0,%1,%2,%3};"
                                 : "+f"(acc[im][in][0]), "+f"(acc[im][in][1]),
                                   "+f"(acc[im][in][2]), "+f"(acc[im][in][3])
                                 : "r"(a[im][0]), "r"(a[im][1]), "r"(a[im][2]), "r"(a[im][3]),
                                   "r"(b[in][0]), "r"(b[in][1]));
        }
        s ^= 1;
        __syncthreads();
    }

    // ---- fused epilogue phase 1: per-row (max, argmax) over warp's 64 cols ----
    // Thread owns rows r = wm + im*16 + half*8 + (lane>>2), cols wn + in*8 + (lane&3)*2 + j.
#pragma unroll
    for (int im = 0; im < 2; im++)
#pragma unroll
        for (int half = 0; half < 2; half++) {
            float m = -3.402823e38f; int id = 0;
#pragma unroll
            for (int in = 0; in < 8; in++)
#pragma unroll
                for (int j = 0; j < 2; j++) {
                    float v = acc[im][in][half * 2 + j];
                    int c = bcol + wn + in * 8 + ((lane & 3) << 1) + j;
                    if (v > m) { m = v; id = c; }       // ascending col -> first kept
                }
            // quad reduce (lanes sharing the same rows)
#pragma unroll
            for (int o = 1; o <= 2; o <<= 1) {
                float om = __shfl_xor_sync(0xffffffffu, m, o);
                int oid = __shfl_xor_sync(0xffffffffu, id, o);
                if (om > m || (om == m && oid < id)) { m = om; id = oid; }
            }
            if ((lane & 3) == 0) {
                int r = wm + im * 16 + half * 8 + (lane >> 2);
                s_max[r][wcol] = m; s_idx[r][wcol] = id;
            }
        }
    __syncthreads();

    // phase 2: sumexp relative to the TILE-WIDE row max M (both warp-columns)
#pragma unroll
    for (int im = 0; im < 2; im++)
#pragma unroll
        for (int half = 0; half < 2; half++) {
            int r = wm + im * 16 + half * 8 + (lane >> 2);
            float m0 = s_max[r][0], m1 = s_max[r][1];
            float M = (m1 > m0) ? m1 : m0;
            float su = 0.f;
#pragma unroll
            for (int in = 0; in < 8; in++)
#pragma unroll
                for (int j = 0; j < 2; j++)
                    su += fexp((acc[im][in][half * 2 + j] - M) * INV_T);
#pragma unroll
            for (int o = 1; o <= 2; o <<= 1)
                su += __shfl_xor_sync(0xffffffffu, su, o);
            if ((lane & 3) == 0) s_sum[r][wcol] = su;
        }
    __syncthreads();

    // phase 3: both halves are already referenced to the tile max M, so the
    // combine is a plain ADD (the previous round double-applied the rescale).
    if (tid < 128) {
        int r = tid;
        float m0 = s_max[r][0], m1 = s_max[r][1];
        float M; int I;
        if (m1 > m0) { M = m1; I = s_idx[r][1]; }
        else         { M = m0; I = s_idx[r][0]; }
        float S = s_sum[r][0] + s_sum[r][1];
        size_t o = (size_t)(brow + r) * NTILE + blockIdx.x;
        g_pmax[o] = M; g_pidx[o] = I; g_psum[o] = S;
    }
}

// ---------------- kernel 3: deterministic merge of tile partials -----------
__global__ __launch_bounds__(256) void merge_kernel() {
    int row  = blockIdx.x * 8 + (threadIdx.x >> 5);
    int lane = threadIdx.x & 31;
    size_t base = (size_t)row * NTILE;

    // each lane combines tiles (lane) and (lane+32), then xor-tree reduce
    float m  = g_pmax[base + lane];
    int   id = g_pidx[base + lane];
    float su = g_psum[base + lane];
    {
        float om = g_pmax[base + lane + 32];
        int  oid = g_pidx[base + lane + 32];
        float os = g_psum[base + lane + 32];
        float M = fmaxf(m, om);
        float S = su * fexp((m - M) * INV_T) + os * fexp((om - M) * INV_T);
        int   I = (om > m || (om == m && oid < id)) ? oid : id;
        m = M; su = S; id = I;
    }
#pragma unroll
    for (int o = 1; o < 32; o <<= 1) {
        float om = __shfl_xor_sync(0xffffffffu, m, o);
        int  oid = __shfl_xor_sync(0xffffffffu, id, o);
        float os = __shfl_xor_sync(0xffffffffu, su, o);
        float M = fmaxf(m, om);
        float S = su * fexp((m - M) * INV_T) + os * fexp((om - M) * INV_T);
        int   I = (om > m || (om == m && oid < id)) ? oid : id;
        m = M; su = S; id = I;
    }
    if (lane == 0) {
        g_logl[row] = logf(su);     // -logp at argmax (positive logit == row max)
        g_pos[row]  = id;
    }
}

// ---------------- kernel 4: nn_sim[i] = <B[pos[i]], B[pos[i+1]]> -----------
__global__ __launch_bounds__(256) void nn_kernel() {
    int i = blockIdx.x * 8 + (threadIdx.x >> 5);        // one warp per i
    if (i >= N_ROWS - 1) return;
    int lane = threadIdx.x & 31;
    const uint4* u = (const uint4*)(g_B + (size_t)g_pos[i]     * H_DIM);
    const uint4* v = (const uint4*)(g_B + (size_t)g_pos[i + 1] * H_DIM);
    float acc = 0.f;
#pragma unroll
    for (int k = 0; k < 4; k++) {                        // 128 uint4 per row
        uint4 a = u[lane + 32 * k];
        uint4 b = v[lane + 32 * k];
        const __nv_bfloat162* pa = (const __nv_bfloat162*)&a;
        const __nv_bfloat162* pb = (const __nv_bfloat162*)&b;
#pragma unroll
        for (int q = 0; q < 4; q++) {
            float2 fa = __bfloat1622float2(pa[q]);
            float2 fb = __bfloat1622float2(pb[q]);
            acc = fmaf(fa.x, fb.x, acc);
            acc = fmaf(fa.y, fb.y, acc);
        }
    }
#pragma unroll
    for (int o = 16; o; o >>= 1) acc += __shfl_xor_sync(0xffffffffu, acc, o);
    if (lane == 0) g_nn[i] = acc;
}

// ---------------- kernel 5: final deterministic reduction ------------------
__global__ __launch_bounds__(256) void final_kernel(float* __restrict__ out) {
    __shared__ float s1[256], s2[256];
    int t = threadIdx.x;
    float a = 0.f, b = 0.f;
    for (int j = t; j < N_ROWS; j += 256) a += g_logl[j];
    for (int j = t; j < N_ROWS - 1; j += 256) b += g_nn[j];
    s1[t] = a; s2[t] = b;
    __syncthreads();
    for (int s = 128; s > 0; s >>= 1) {
        if (t < s) { s1[t] += s1[t + s]; s2[t] += s2[t + s]; }
        __syncthreads();
    }
    if (t == 0) {
        out[0] = s1[0] / (float)N_ROWS;                // l_contrastive
        out[1] = 1.0f - s2[0] / (float)(N_ROWS - 1);   // l_contextual
    }
}

// ---------------- launcher --------------------------------------------------
extern "C" void kernel_launch(void* const* d_in, const int* in_sizes, int n_in,
                              void* d_out, int out_size) {
    const float* h_source = (const float*)d_in[0];
    const float* h_target = (const float*)d_in[1];
    float* out = (float*)d_out;

    norm_kernel<<<2 * N_ROWS, 256>>>(h_source, h_target);
    dim3 grid(N_ROWS / 128, N_ROWS / 128);
    gemm_fused_kernel<<<grid, 256>>>();
    merge_kernel<<<N_ROWS / 8, 256>>>();
    nn_kernel<<<N_ROWS / 8, 256>>>();
    final_kernel<<<1, 256>>>(out);
}

// round 5
// speedup vs baseline: 1.4650x; 1.2902x over previous
#include <cuda_runtime.h>
#include <cuda_bf16.h>
#include <cstdint>
#include <math.h>

#define N_ROWS 8192
#define H_DIM  1024
#define NTILE  32                    // N_ROWS / 256 column tiles
#define INV_T  (1.0f/0.07f)
#define EX2_SCALE 20.609929f         // INV_T * log2(e)

// GEMM tiling: CTA 128(M) x 256(N), BK=64, 4 stages, 8 warps of 64x64
#define TM 128
#define TN 256
#define KC 64
#define KT_STEPS (H_DIM / KC)        // 16
#define ST 4
#define A_BYTES (TM * 128)           // 16 KB  (128 rows x 128 B)
#define B_BYTES (TN * 128)           // 32 KB
#define STAGE_BYTES (A_BYTES + B_BYTES)      // 48 KB
#define SMEM_DYN (1024 + ST * STAGE_BYTES)   // 197,632 B

// ---------------- scratch (device globals; no runtime allocation) ----------
__device__ __nv_bfloat16 g_A[(size_t)N_ROWS * H_DIM];
__device__ __nv_bfloat16 g_B[(size_t)N_ROWS * H_DIM];
__device__ float g_pmax[(size_t)N_ROWS * NTILE];
__device__ int   g_pidx[(size_t)N_ROWS * NTILE];
__device__ float g_psum[(size_t)N_ROWS * NTILE];   // relative to g_pmax
__device__ float g_logl[N_ROWS];
__device__ int   g_pos[N_ROWS];
__device__ float g_nn[N_ROWS];

// ---------------- helpers ---------------------------------------------------
__device__ __forceinline__ void cp16s(uint32_t s, const void* g) {
    asm volatile("cp.async.cg.shared.global [%0], [%1], 16;" :: "r"(s), "l"(g));
}
__device__ __forceinline__ float fex2(float x) {
    float y; asm("ex2.approx.f32 %0, %1;" : "=f"(y) : "f"(x)); return y;
}
// exp(x) on FMA pipe for the merge kernel (x <= 0)
__device__ __forceinline__ float fexp(float x) {
    float t = x * 1.4426950408889634f;
    float fl = floorf(t);
    float f = t - fl;
    float p = 1.5403530e-4f;
    p = fmaf(p, f, 1.3333558e-3f);
    p = fmaf(p, f, 9.6181291e-3f);
    p = fmaf(p, f, 5.5504110e-2f);
    p = fmaf(p, f, 2.4022651e-1f);
    p = fmaf(p, f, 6.9314718e-1f);
    p = fmaf(p, f, 1.0f);
    return __int_as_float((uint32_t)((int)fl + 127) << 23) * p;
}
__device__ __forceinline__ uint32_t sw128(uint32_t off) {   // Swizzle<3,4,3>
    return off ^ ((off >> 3) & 0x70);
}

// ---------------- kernel 1: row L2-normalize -> bf16 -----------------------
__global__ __launch_bounds__(256) void norm_kernel(const float* __restrict__ src,
                                                   const float* __restrict__ tgt) {
    int row = blockIdx.x;
    const float* in;
    __nv_bfloat16* out;
    if (row < N_ROWS) { in = src + (size_t)row * H_DIM;            out = g_A + (size_t)row * H_DIM; }
    else              { in = tgt + (size_t)(row - N_ROWS) * H_DIM; out = g_B + (size_t)(row - N_ROWS) * H_DIM; }

    int t = threadIdx.x;
    float v[4];
    float ss = 0.f;
#pragma unroll
    for (int j = 0; j < 4; j++) { v[j] = in[t + 256 * j]; ss += v[j] * v[j]; }
#pragma unroll
    for (int o = 16; o; o >>= 1) ss += __shfl_xor_sync(0xffffffffu, ss, o);
    __shared__ float red[8];
    if ((t & 31) == 0) red[t >> 5] = ss;
    __syncthreads();
    float total = red[0] + red[1] + red[2] + red[3] + red[4] + red[5] + red[6] + red[7];
    float sc = 1.0f / fmaxf(sqrtf(total), 1e-12f);
#pragma unroll
    for (int j = 0; j < 4; j++) out[t + 256 * j] = __float2bfloat16(v[j] * sc);
}

// ---------------- kernel 2: HMMA GEMM (128x256) + fused softmax partials ----
__global__ __launch_bounds__(256, 1) void gemm_fused_kernel() {
    extern __shared__ __align__(16) char dsm[];
    uint32_t raw  = (uint32_t)__cvta_generic_to_shared(dsm);
    uint32_t base = (raw + 1023u) & ~1023u;

    const int tid   = threadIdx.x;
    const int lane  = tid & 31;
    const int warp  = tid >> 5;
    const int warpM = warp >> 2;            // 0..1  -> rows  warpM*64
    const int warpN = warp & 3;             // 0..3  -> cols  warpN*64
    const int wm = warpM * 64;
    const int wn = warpN * 64;
    const int brow = blockIdx.y * TM;
    const int bcol = blockIdx.x * TN;

    float acc[4][8][4];
#pragma unroll
    for (int im = 0; im < 4; im++)
#pragma unroll
        for (int in = 0; in < 8; in++)
#pragma unroll
            for (int k = 0; k < 4; k++) acc[im][in][k] = 0.f;

    // stage fill: A 1024 chunks of 16B, B 2048 chunks; 12 cp.async per thread
    auto load_stage = [&](int s, int kt) {
        const char* gA = (const char*)g_A + (size_t)brow * (H_DIM * 2) + kt * (KC * 2);
        const char* gB = (const char*)g_B + (size_t)bcol * (H_DIM * 2) + kt * (KC * 2);
        uint32_t aB = base + s * STAGE_BYTES;
        uint32_t bB = aB + A_BYTES;
#pragma unroll
        for (int i = tid; i < TM * 8; i += 256) {
            int r = i >> 3, c = i & 7;
            cp16s(aB + sw128((uint32_t)(r * 128 + c * 16)), gA + (size_t)r * (H_DIM * 2) + c * 16);
        }
#pragma unroll
        for (int i = tid; i < TN * 8; i += 256) {
            int r = i >> 3, c = i & 7;
            cp16s(bB + sw128((uint32_t)(r * 128 + c * 16)), gB + (size_t)r * (H_DIM * 2) + c * 16);
        }
    };

    // prefill 3 stages
#pragma unroll
    for (int p = 0; p < ST - 1; p++) {
        load_stage(p, p);
        asm volatile("cp.async.commit_group;");
    }

    for (int kt = 0; kt < KT_STEPS; kt++) {
        int s = kt & (ST - 1);
        asm volatile("cp.async.wait_group %0;" :: "n"(ST - 2));
        __syncthreads();                       // stage s ready; all warps done with s's prior life

        if (kt + ST - 1 < KT_STEPS) load_stage((kt + ST - 1) & (ST - 1), kt + ST - 1);
        asm volatile("cp.async.commit_group;"); // uniform group accounting

        uint32_t aT = base + s * STAGE_BYTES;
        uint32_t bT = aT + A_BYTES;
#pragma unroll
        for (int ks = 0; ks < KC; ks += 16) {
            uint32_t a[4][4], b[8][2];
#pragma unroll
            for (int im = 0; im < 4; im++) {
                uint32_t off = (uint32_t)((wm + im * 16 + (lane & 15)) * 128
                                          + (ks + ((lane >> 4) << 3)) * 2);
                uint32_t addr = aT + sw128(off);
                asm volatile("ldmatrix.sync.aligned.m8n8.x4.shared.b16 {%0,%1,%2,%3}, [%4];"
                             : "=r"(a[im][0]), "=r"(a[im][1]), "=r"(a[im][2]), "=r"(a[im][3])
                             : "r"(addr));
            }
#pragma unroll
            for (int ib = 0; ib < 4; ib++) {
                uint32_t off = (uint32_t)((wn + ib * 16 + ((lane >> 4) << 3) + (lane & 7)) * 128
                                          + (ks + (((lane >> 3) & 1) << 3)) * 2);
                uint32_t addr = bT + sw128(off);
                uint32_t r0, r1, r2, r3;
                asm volatile("ldmatrix.sync.aligned.m8n8.x4.shared.b16 {%0,%1,%2,%3}, [%4];"
                             : "=r"(r0), "=r"(r1), "=r"(r2), "=r"(r3) : "r"(addr));
                b[2 * ib][0] = r0; b[2 * ib][1] = r1;
                b[2 * ib + 1][0] = r2; b[2 * ib + 1][1] = r3;
            }
#pragma unroll
            for (int im = 0; im < 4; im++)
#pragma unroll
                for (int in = 0; in < 8; in++)
                    asm volatile("mma.sync.aligned.m16n8k16.row.col.f32.bf16.bf16.f32 "
                                 "{%0,%1,%2,%3},{%4,%5,%6,%7},{%8,%9},{%0,%1,%2,%3};"
                                 : "+f"(acc[im][in][0]), "+f"(acc[im][in][1]),
                                   "+f"(acc[im][in][2]), "+f"(acc[im][in][3])
                                 : "r"(a[im][0]), "r"(a[im][1]), "r"(a[im][2]), "r"(a[im][3]),
                                   "r"(b[in][0]), "r"(b[in][1]));
        }
        __syncthreads();
    }

    // ---- epilogue: reuse stage SMEM for per-row partials ----
    float* s_max = (float*)(dsm + (base - raw));          // [128][4]
    int*   s_idx = (int*)  (s_max + 128 * 4);
    float* s_sum = (float*)(s_idx + 128 * 4);

    // phase 1: per-warp (max, argmax) over its 64 cols
#pragma unroll
    for (int im = 0; im < 4; im++)
#pragma unroll
        for (int half = 0; half < 2; half++) {
            float m = -3.402823e38f; int id = 0;
#pragma unroll
            for (int in = 0; in < 8; in++)
#pragma unroll
                for (int j = 0; j < 2; j++) {
                    float v = acc[im][in][half * 2 + j];
                    int c = bcol + wn + in * 8 + ((lane & 3) << 1) + j;
                    if (v > m) { m = v; id = c; }          // ascending -> first kept
                }
#pragma unroll
            for (int o = 1; o <= 2; o <<= 1) {
                float om = __shfl_xor_sync(0xffffffffu, m, o);
                int  oid = __shfl_xor_sync(0xffffffffu, id, o);
                if (om > m || (om == m && oid < id)) { m = om; id = oid; }
            }
            if ((lane & 3) == 0) {
                int r = wm + im * 16 + half * 8 + (lane >> 2);
                s_max[r * 4 + warpN] = m; s_idx[r * 4 + warpN] = id;
            }
        }
    __syncthreads();

    // phase 2: sumexp relative to the TILE-WIDE row max
#pragma unroll
    for (int im = 0; im < 4; im++)
#pragma unroll
        for (int half = 0; half < 2; half++) {
            int r = wm + im * 16 + half * 8 + (lane >> 2);
            float M = fmaxf(fmaxf(s_max[r * 4 + 0], s_max[r * 4 + 1]),
                            fmaxf(s_max[r * 4 + 2], s_max[r * 4 + 3]));
            float su = 0.f;
#pragma unroll
            for (int in = 0; in < 8; in++)
#pragma unroll
                for (int j = 0; j < 2; j++)
                    su += fex2((acc[im][in][half * 2 + j] - M) * EX2_SCALE);
#pragma unroll
            for (int o = 1; o <= 2; o <<= 1)
                su += __shfl_xor_sync(0xffffffffu, su, o);
            if ((lane & 3) == 0) s_sum[r * 4 + warpN] = su;
        }
    __syncthreads();

    // phase 3: combine 4 warp-columns (all already relative to tile max)
    if (tid < 128) {
        int r = tid;
        float M = s_max[r * 4 + 0]; int I = s_idx[r * 4 + 0];
#pragma unroll
        for (int c = 1; c < 4; c++) {
            float om = s_max[r * 4 + c]; int oid = s_idx[r * 4 + c];
            if (om > M || (om == M && oid < I)) { M = om; I = oid; }
        }
        float S = s_sum[r * 4 + 0] + s_sum[r * 4 + 1] + s_sum[r * 4 + 2] + s_sum[r * 4 + 3];
        size_t o = (size_t)(brow + r) * NTILE + blockIdx.x;
        g_pmax[o] = M; g_pidx[o] = I; g_psum[o] = S;
    }
}

// ---------------- kernel 3: merge 32 tile partials per row (1 warp/row) ----
__global__ __launch_bounds__(256) void merge_kernel() {
    int row  = blockIdx.x * 8 + (threadIdx.x >> 5);
    int lane = threadIdx.x & 31;
    size_t b = (size_t)row * NTILE;
    float m  = g_pmax[b + lane];
    int   id = g_pidx[b + lane];
    float su = g_psum[b + lane];
#pragma unroll
    for (int o = 1; o < 32; o <<= 1) {
        float om = __shfl_xor_sync(0xffffffffu, m, o);
        int  oid = __shfl_xor_sync(0xffffffffu, id, o);
        float os = __shfl_xor_sync(0xffffffffu, su, o);
        float M = fmaxf(m, om);
        float S = su * fexp((m - M) * INV_T) + os * fexp((om - M) * INV_T);
        int   I = (om > m || (om == m && oid < id)) ? oid : id;
        m = M; su = S; id = I;
    }
    if (lane == 0) {
        g_logl[row] = logf(su);      // -logp at argmax (positive logit == row max)
        g_pos[row]  = id;
    }
}

// ---------------- kernel 4: nn_sim[i] = <B[pos[i]], B[pos[i+1]]> -----------
__global__ __launch_bounds__(256) void nn_kernel() {
    int i = blockIdx.x * 8 + (threadIdx.x >> 5);
    if (i >= N_ROWS - 1) return;
    int lane = threadIdx.x & 31;
    const uint4* u = (const uint4*)(g_B + (size_t)g_pos[i]     * H_DIM);
    const uint4* v = (const uint4*)(g_B + (size_t)g_pos[i + 1] * H_DIM);
    float acc = 0.f;
#pragma unroll
    for (int k = 0; k < 4; k++) {
        uint4 a = u[lane + 32 * k];
        uint4 b = v[lane + 32 * k];
        const __nv_bfloat162* pa = (const __nv_bfloat162*)&a;
        const __nv_bfloat162* pb = (const __nv_bfloat162*)&b;
#pragma unroll
        for (int q = 0; q < 4; q++) {
            float2 fa = __bfloat1622float2(pa[q]);
            float2 fb = __bfloat1622float2(pb[q]);
            acc = fmaf(fa.x, fb.x, acc);
            acc = fmaf(fa.y, fb.y, acc);
        }
    }
#pragma unroll
    for (int o = 16; o; o >>= 1) acc += __shfl_xor_sync(0xffffffffu, acc, o);
    if (lane == 0) g_nn[i] = acc;
}

// ---------------- kernel 5: final deterministic reduction ------------------
__global__ __launch_bounds__(256) void final_kernel(float* __restrict__ out) {
    __shared__ float s1[256], s2[256];
    int t = threadIdx.x;
    float a = 0.f, b = 0.f;
    for (int j = t; j < N_ROWS; j += 256) a += g_logl[j];
    for (int j = t; j < N_ROWS - 1; j += 256) b += g_nn[j];
    s1[t] = a; s2[t] = b;
    __syncthreads();
    for (int s = 128; s > 0; s >>= 1) {
        if (t < s) { s1[t] += s1[t + s]; s2[t] += s2[t + s]; }
        __syncthreads();
    }
    if (t == 0) {
        out[0] = s1[0] / (float)N_ROWS;
        out[1] = 1.0f - s2[0] / (float)(N_ROWS - 1);
    }
}

// ---------------- launcher --------------------------------------------------
extern "C" void kernel_launch(void* const* d_in, const int* in_sizes, int n_in,
                              void* d_out, int out_size) {
    const float* h_source = (const float*)d_in[0];
    const float* h_target = (const float*)d_in[1];
    float* out = (float*)d_out;

    norm_kernel<<<2 * N_ROWS, 256>>>(h_source, h_target);

    cudaFuncSetAttribute(gemm_fused_kernel, cudaFuncAttributeMaxDynamicSharedMemorySize, SMEM_DYN);
    dim3 grid(N_ROWS / TN, N_ROWS / TM);   // 32 x 64
    gemm_fused_kernel<<<grid, 256, SMEM_DYN>>>();

    merge_kernel<<<N_ROWS / 8, 256>>>();
    nn_kernel<<<N_ROWS / 8, 256>>>();
    final_kernel<<<1, 256>>>(out);
}